// round 12
// baseline (speedup 1.0000x reference)
#include <cuda_runtime.h>
#include <cuda_bf16.h>
#include <cstdint>

// PFNLayer pillar feature decoration — FINAL (converged after 11 rounds).
// Fused single kernel, 2 pillars per warp, MLP=2 at 86% occupancy (regs 32),
// streaming loads (__ldcs) and stores (__stcs), no smem, no barriers.
// Measured: kernel 49.8-51.6us (run noise), 6.6-6.8 TB/s combined nominal
// traffic = ~84% of HBM3e spec — the achieved mixed r/w roofline.
// Falsified alternatives: smem-staged writes (-38%), MLP=3/4 (occ crash),
// default-cached reads (write stream thrashes L2), front-batching (neutral),
// occupancy caps (worse).
//
//   pillars:  (P, 32, 4) f32
//   coors:    (P, 4)     i32
//   npoints:  (P,)       i32
// Output buffer: [coors cast to f32 (P*4)] ++ [features (P,9,32) f32]
// features:
//   ch0 = x - (coors[:,1]*0.16 + 0.08)
//   ch1 = y - (coors[:,2]*0.16 + 0.08)   // upstream bug: x_offset for y, replicated
//   ch2 = z, ch3 = w
//   ch4..6 = xyz - mean_xyz  (mean = sum over ALL 32 slots / true count n)
//   ch7 = ch0, ch8 = ch1
//   channels zeroed for slot j >= n

static constexpr int MAX_PTS = 32;
static constexpr float VOXEL = 0.16f;
static constexpr float OFFSET = 0.08f;   // voxel/2 + 0.0, used for BOTH x and y (ref bug)

static constexpr int WARPS_PER_BLOCK = 8;
static constexpr int PILLARS_PER_WARP = 2;
static constexpr int PILLARS_PER_BLOCK = WARPS_PER_BLOCK * PILLARS_PER_WARP;  // 16
static constexpr int FEAT_FLOATS = 9 * MAX_PTS;          // 288 floats per pillar

__global__ void __launch_bounds__(256)
pfn_fused_kernel(const float4* __restrict__ pillars,   // (P*32) float4
                 const int4*   __restrict__ coors,     // (P) int4
                 const int*    __restrict__ npts,      // (P)
                 float*        __restrict__ out_coors, // (P*4) or nullptr
                 float*        __restrict__ out_feat,  // (P*9*32)
                 int P)
{
    const int warp_in_block = threadIdx.x >> 5;
    const int lane = threadIdx.x & 31;
    const long long pbase = (long long)blockIdx.x * PILLARS_PER_BLOCK
                          + warp_in_block * PILLARS_PER_WARP;
    const int p0 = (int)pbase;
    const int p1 = p0 + 1;
    const bool has0 = (p0 < P);
    const bool has1 = (p1 < P);

    // two independent 128-bit loads per lane — MLP=2, both streaming
    float4 v0 = make_float4(0.f, 0.f, 0.f, 0.f);
    float4 v1 = make_float4(0.f, 0.f, 0.f, 0.f);
    if (has0) v0 = __ldcs(&pillars[(long long)p0 * MAX_PTS + lane]);
    if (has1) v1 = __ldcs(&pillars[(long long)p1 * MAX_PTS + lane]);

    // interleaved warp reductions (sum over ALL 32 slots, per reference)
    float s0x = v0.x, s0y = v0.y, s0z = v0.z;
    float s1x = v1.x, s1y = v1.y, s1z = v1.z;
    #pragma unroll
    for (int ofs = 16; ofs > 0; ofs >>= 1) {
        s0x += __shfl_xor_sync(0xFFFFFFFFu, s0x, ofs);
        s1x += __shfl_xor_sync(0xFFFFFFFFu, s1x, ofs);
        s0y += __shfl_xor_sync(0xFFFFFFFFu, s0y, ofs);
        s1y += __shfl_xor_sync(0xFFFFFFFFu, s1y, ofs);
        s0z += __shfl_xor_sync(0xFFFFFFFFu, s0z, ofs);
        s1z += __shfl_xor_sync(0xFFFFFFFFu, s1z, ofs);
    }

    if (has0) {
        const int   n    = __ldg(&npts[p0]);
        const float invn = 1.0f / (float)n;
        const int4  c    = __ldg(&coors[p0]);
        if (out_coors != nullptr && lane == 0) {
            float4 cf = make_float4((float)c.x, (float)c.y, (float)c.z, (float)c.w);
            __stcs(reinterpret_cast<float4*>(out_coors) + p0, cf);
        }
        const float cx = (float)c.y * VOXEL + OFFSET;
        const float cy = (float)c.z * VOXEL + OFFSET;  // ref bug: x_offset for y
        const float m  = (lane < n) ? 1.0f : 0.0f;
        const float off_x = (v0.x - cx) * m;
        const float off_y = (v0.y - cy) * m;
        float* o = out_feat + (long long)p0 * FEAT_FLOATS + lane;
        __stcs(&o[0 * 32], off_x);
        __stcs(&o[1 * 32], off_y);
        __stcs(&o[2 * 32], v0.z * m);
        __stcs(&o[3 * 32], v0.w * m);
        __stcs(&o[4 * 32], (v0.x - s0x * invn) * m);
        __stcs(&o[5 * 32], (v0.y - s0y * invn) * m);
        __stcs(&o[6 * 32], (v0.z - s0z * invn) * m);
        __stcs(&o[7 * 32], off_x);
        __stcs(&o[8 * 32], off_y);
    }

    if (has1) {
        const int   n    = __ldg(&npts[p1]);
        const float invn = 1.0f / (float)n;
        const int4  c    = __ldg(&coors[p1]);
        if (out_coors != nullptr && lane == 0) {
            float4 cf = make_float4((float)c.x, (float)c.y, (float)c.z, (float)c.w);
            __stcs(reinterpret_cast<float4*>(out_coors) + p1, cf);
        }
        const float cx = (float)c.y * VOXEL + OFFSET;
        const float cy = (float)c.z * VOXEL + OFFSET;  // ref bug: x_offset for y
        const float m  = (lane < n) ? 1.0f : 0.0f;
        const float off_x = (v1.x - cx) * m;
        const float off_y = (v1.y - cy) * m;
        float* o = out_feat + (long long)p1 * FEAT_FLOATS + lane;
        __stcs(&o[0 * 32], off_x);
        __stcs(&o[1 * 32], off_y);
        __stcs(&o[2 * 32], v1.z * m);
        __stcs(&o[3 * 32], v1.w * m);
        __stcs(&o[4 * 32], (v1.x - s1x * invn) * m);
        __stcs(&o[5 * 32], (v1.y - s1y * invn) * m);
        __stcs(&o[6 * 32], (v1.z - s1z * invn) * m);
        __stcs(&o[7 * 32], off_x);
        __stcs(&o[8 * 32], off_y);
    }
}

extern "C" void kernel_launch(void* const* d_in, const int* in_sizes, int n_in,
                              void* d_out, int out_size)
{
    const float* pillars = (const float*)d_in[0];
    const int*   coors   = (const int*)d_in[1];
    const int*   npts    = (const int*)d_in[2];
    float* out = (float*)d_out;

    const long long P = (long long)in_sizes[2];          // npoints count = P
    const long long coors_elems = P * 4;
    const long long feat_elems  = P * 9 * MAX_PTS;

    float* out_coors = nullptr;
    float* out_feat  = out;
    if ((long long)out_size >= coors_elems + feat_elems) {
        out_coors = out;
        out_feat  = out + coors_elems;
    }

    const int blocks = (int)((P + PILLARS_PER_BLOCK - 1) / PILLARS_PER_BLOCK);
    pfn_fused_kernel<<<blocks, 256>>>(
        (const float4*)pillars, (const int4*)coors, npts, out_coors, out_feat, (int)P);
}

// round 13
// speedup vs baseline: 1.0018x; 1.0018x over previous
#include <cuda_runtime.h>
#include <cuda_bf16.h>
#include <cstdint>

// PFNLayer pillar feature decoration — FINAL (converged; rounds 9/11/12 show
// identical binary at kernel 49.8-51.6us, the run-to-run noise band).
// Fused single kernel, 2 pillars per warp, MLP=2 at ~86% occupancy (regs 32),
// streaming loads (__ldcs) and stores (__stcs), no smem, no barriers.
// 336 MB nominal traffic at 6.6-6.8 TB/s = ~84% of HBM3e spec — the achieved
// mixed read/write roofline on sm_103a.
// Falsified alternatives: smem-staged writes (-38%), MLP=3/4 (occupancy
// crash), default-cached reads (write stream thrashes L2), front-batching
// (neutral-to-worse), occupancy caps (worse), separate coors kernel (+6us).
//
//   pillars:  (P, 32, 4) f32
//   coors:    (P, 4)     i32
//   npoints:  (P,)       i32
// Output buffer: [coors cast to f32 (P*4)] ++ [features (P,9,32) f32]
// features:
//   ch0 = x - (coors[:,1]*0.16 + 0.08)
//   ch1 = y - (coors[:,2]*0.16 + 0.08)   // upstream bug: x_offset for y, replicated
//   ch2 = z, ch3 = w
//   ch4..6 = xyz - mean_xyz  (mean = sum over ALL 32 slots / true count n)
//   ch7 = ch0, ch8 = ch1
//   channels zeroed for slot j >= n

static constexpr int MAX_PTS = 32;
static constexpr float VOXEL = 0.16f;
static constexpr float OFFSET = 0.08f;   // voxel/2 + 0.0, used for BOTH x and y (ref bug)

static constexpr int WARPS_PER_BLOCK = 8;
static constexpr int PILLARS_PER_WARP = 2;
static constexpr int PILLARS_PER_BLOCK = WARPS_PER_BLOCK * PILLARS_PER_WARP;  // 16
static constexpr int FEAT_FLOATS = 9 * MAX_PTS;          // 288 floats per pillar

__global__ void __launch_bounds__(256)
pfn_fused_kernel(const float4* __restrict__ pillars,   // (P*32) float4
                 const int4*   __restrict__ coors,     // (P) int4
                 const int*    __restrict__ npts,      // (P)
                 float*        __restrict__ out_coors, // (P*4) or nullptr
                 float*        __restrict__ out_feat,  // (P*9*32)
                 int P)
{
    const int warp_in_block = threadIdx.x >> 5;
    const int lane = threadIdx.x & 31;
    const long long pbase = (long long)blockIdx.x * PILLARS_PER_BLOCK
                          + warp_in_block * PILLARS_PER_WARP;
    const int p0 = (int)pbase;
    const int p1 = p0 + 1;
    const bool has0 = (p0 < P);
    const bool has1 = (p1 < P);

    // two independent 128-bit loads per lane — MLP=2, both streaming
    float4 v0 = make_float4(0.f, 0.f, 0.f, 0.f);
    float4 v1 = make_float4(0.f, 0.f, 0.f, 0.f);
    if (has0) v0 = __ldcs(&pillars[(long long)p0 * MAX_PTS + lane]);
    if (has1) v1 = __ldcs(&pillars[(long long)p1 * MAX_PTS + lane]);

    // interleaved warp reductions (sum over ALL 32 slots, per reference)
    float s0x = v0.x, s0y = v0.y, s0z = v0.z;
    float s1x = v1.x, s1y = v1.y, s1z = v1.z;
    #pragma unroll
    for (int ofs = 16; ofs > 0; ofs >>= 1) {
        s0x += __shfl_xor_sync(0xFFFFFFFFu, s0x, ofs);
        s1x += __shfl_xor_sync(0xFFFFFFFFu, s1x, ofs);
        s0y += __shfl_xor_sync(0xFFFFFFFFu, s0y, ofs);
        s1y += __shfl_xor_sync(0xFFFFFFFFu, s1y, ofs);
        s0z += __shfl_xor_sync(0xFFFFFFFFu, s0z, ofs);
        s1z += __shfl_xor_sync(0xFFFFFFFFu, s1z, ofs);
    }

    if (has0) {
        const int   n    = __ldg(&npts[p0]);
        const float invn = 1.0f / (float)n;
        const int4  c    = __ldg(&coors[p0]);
        if (out_coors != nullptr && lane == 0) {
            float4 cf = make_float4((float)c.x, (float)c.y, (float)c.z, (float)c.w);
            __stcs(reinterpret_cast<float4*>(out_coors) + p0, cf);
        }
        const float cx = (float)c.y * VOXEL + OFFSET;
        const float cy = (float)c.z * VOXEL + OFFSET;  // ref bug: x_offset for y
        const float m  = (lane < n) ? 1.0f : 0.0f;
        const float off_x = (v0.x - cx) * m;
        const float off_y = (v0.y - cy) * m;
        float* o = out_feat + (long long)p0 * FEAT_FLOATS + lane;
        __stcs(&o[0 * 32], off_x);
        __stcs(&o[1 * 32], off_y);
        __stcs(&o[2 * 32], v0.z * m);
        __stcs(&o[3 * 32], v0.w * m);
        __stcs(&o[4 * 32], (v0.x - s0x * invn) * m);
        __stcs(&o[5 * 32], (v0.y - s0y * invn) * m);
        __stcs(&o[6 * 32], (v0.z - s0z * invn) * m);
        __stcs(&o[7 * 32], off_x);
        __stcs(&o[8 * 32], off_y);
    }

    if (has1) {
        const int   n    = __ldg(&npts[p1]);
        const float invn = 1.0f / (float)n;
        const int4  c    = __ldg(&coors[p1]);
        if (out_coors != nullptr && lane == 0) {
            float4 cf = make_float4((float)c.x, (float)c.y, (float)c.z, (float)c.w);
            __stcs(reinterpret_cast<float4*>(out_coors) + p1, cf);
        }
        const float cx = (float)c.y * VOXEL + OFFSET;
        const float cy = (float)c.z * VOXEL + OFFSET;  // ref bug: x_offset for y
        const float m  = (lane < n) ? 1.0f : 0.0f;
        const float off_x = (v1.x - cx) * m;
        const float off_y = (v1.y - cy) * m;
        float* o = out_feat + (long long)p1 * FEAT_FLOATS + lane;
        __stcs(&o[0 * 32], off_x);
        __stcs(&o[1 * 32], off_y);
        __stcs(&o[2 * 32], v1.z * m);
        __stcs(&o[3 * 32], v1.w * m);
        __stcs(&o[4 * 32], (v1.x - s1x * invn) * m);
        __stcs(&o[5 * 32], (v1.y - s1y * invn) * m);
        __stcs(&o[6 * 32], (v1.z - s1z * invn) * m);
        __stcs(&o[7 * 32], off_x);
        __stcs(&o[8 * 32], off_y);
    }
}

extern "C" void kernel_launch(void* const* d_in, const int* in_sizes, int n_in,
                              void* d_out, int out_size)
{
    const float* pillars = (const float*)d_in[0];
    const int*   coors   = (const int*)d_in[1];
    const int*   npts    = (const int*)d_in[2];
    float* out = (float*)d_out;

    const long long P = (long long)in_sizes[2];          // npoints count = P
    const long long coors_elems = P * 4;
    const long long feat_elems  = P * 9 * MAX_PTS;

    float* out_coors = nullptr;
    float* out_feat  = out;
    if ((long long)out_size >= coors_elems + feat_elems) {
        out_coors = out;
        out_feat  = out + coors_elems;
    }

    const int blocks = (int)((P + PILLARS_PER_BLOCK - 1) / PILLARS_PER_BLOCK);
    pfn_fused_kernel<<<blocks, 256>>>(
        (const float4*)pillars, (const int4*)coors, npts, out_coors, out_feat, (int)P);
}

// round 14
// speedup vs baseline: 1.0178x; 1.0160x over previous
#include <cuda_runtime.h>
#include <cuda_bf16.h>
#include <cstdint>

// PFNLayer pillar feature decoration — converged configuration, 512-thread
// blocks (16 warps × 2 pillars/warp) to halve CTA count; per-thread code is
// byte-identical to the measured-best 256-thread variant (regs 32, occ ~86%).
// Streaming loads (__ldcs) / stores (__stcs), no smem, no barriers.
// 336 MB nominal traffic at ~6.7 TB/s = ~84% of HBM3e spec (mixed r/w ceiling).
//
//   pillars:  (P, 32, 4) f32
//   coors:    (P, 4)     i32
//   npoints:  (P,)       i32
// Output buffer: [coors cast to f32 (P*4)] ++ [features (P,9,32) f32]
// features:
//   ch0 = x - (coors[:,1]*0.16 + 0.08)
//   ch1 = y - (coors[:,2]*0.16 + 0.08)   // upstream bug: x_offset for y, replicated
//   ch2 = z, ch3 = w
//   ch4..6 = xyz - mean_xyz  (mean = sum over ALL 32 slots / true count n)
//   ch7 = ch0, ch8 = ch1
//   channels zeroed for slot j >= n

static constexpr int MAX_PTS = 32;
static constexpr float VOXEL = 0.16f;
static constexpr float OFFSET = 0.08f;   // voxel/2 + 0.0, used for BOTH x and y (ref bug)

static constexpr int THREADS = 512;
static constexpr int WARPS_PER_BLOCK = THREADS / 32;     // 16
static constexpr int PILLARS_PER_WARP = 2;
static constexpr int PILLARS_PER_BLOCK = WARPS_PER_BLOCK * PILLARS_PER_WARP;  // 32
static constexpr int FEAT_FLOATS = 9 * MAX_PTS;          // 288 floats per pillar

__global__ void __launch_bounds__(THREADS)
pfn_fused_kernel(const float4* __restrict__ pillars,   // (P*32) float4
                 const int4*   __restrict__ coors,     // (P) int4
                 const int*    __restrict__ npts,      // (P)
                 float*        __restrict__ out_coors, // (P*4) or nullptr
                 float*        __restrict__ out_feat,  // (P*9*32)
                 int P)
{
    const int warp_in_block = threadIdx.x >> 5;
    const int lane = threadIdx.x & 31;
    const long long pbase = (long long)blockIdx.x * PILLARS_PER_BLOCK
                          + warp_in_block * PILLARS_PER_WARP;
    const int p0 = (int)pbase;
    const int p1 = p0 + 1;
    const bool has0 = (p0 < P);
    const bool has1 = (p1 < P);

    // two independent 128-bit loads per lane — MLP=2, both streaming
    float4 v0 = make_float4(0.f, 0.f, 0.f, 0.f);
    float4 v1 = make_float4(0.f, 0.f, 0.f, 0.f);
    if (has0) v0 = __ldcs(&pillars[(long long)p0 * MAX_PTS + lane]);
    if (has1) v1 = __ldcs(&pillars[(long long)p1 * MAX_PTS + lane]);

    // interleaved warp reductions (sum over ALL 32 slots, per reference)
    float s0x = v0.x, s0y = v0.y, s0z = v0.z;
    float s1x = v1.x, s1y = v1.y, s1z = v1.z;
    #pragma unroll
    for (int ofs = 16; ofs > 0; ofs >>= 1) {
        s0x += __shfl_xor_sync(0xFFFFFFFFu, s0x, ofs);
        s1x += __shfl_xor_sync(0xFFFFFFFFu, s1x, ofs);
        s0y += __shfl_xor_sync(0xFFFFFFFFu, s0y, ofs);
        s1y += __shfl_xor_sync(0xFFFFFFFFu, s1y, ofs);
        s0z += __shfl_xor_sync(0xFFFFFFFFu, s0z, ofs);
        s1z += __shfl_xor_sync(0xFFFFFFFFu, s1z, ofs);
    }

    if (has0) {
        const int   n    = __ldg(&npts[p0]);
        const float invn = 1.0f / (float)n;
        const int4  c    = __ldg(&coors[p0]);
        if (out_coors != nullptr && lane == 0) {
            float4 cf = make_float4((float)c.x, (float)c.y, (float)c.z, (float)c.w);
            __stcs(reinterpret_cast<float4*>(out_coors) + p0, cf);
        }
        const float cx = (float)c.y * VOXEL + OFFSET;
        const float cy = (float)c.z * VOXEL + OFFSET;  // ref bug: x_offset for y
        const float m  = (lane < n) ? 1.0f : 0.0f;
        const float off_x = (v0.x - cx) * m;
        const float off_y = (v0.y - cy) * m;
        float* o = out_feat + (long long)p0 * FEAT_FLOATS + lane;
        __stcs(&o[0 * 32], off_x);
        __stcs(&o[1 * 32], off_y);
        __stcs(&o[2 * 32], v0.z * m);
        __stcs(&o[3 * 32], v0.w * m);
        __stcs(&o[4 * 32], (v0.x - s0x * invn) * m);
        __stcs(&o[5 * 32], (v0.y - s0y * invn) * m);
        __stcs(&o[6 * 32], (v0.z - s0z * invn) * m);
        __stcs(&o[7 * 32], off_x);
        __stcs(&o[8 * 32], off_y);
    }

    if (has1) {
        const int   n    = __ldg(&npts[p1]);
        const float invn = 1.0f / (float)n;
        const int4  c    = __ldg(&coors[p1]);
        if (out_coors != nullptr && lane == 0) {
            float4 cf = make_float4((float)c.x, (float)c.y, (float)c.z, (float)c.w);
            __stcs(reinterpret_cast<float4*>(out_coors) + p1, cf);
        }
        const float cx = (float)c.y * VOXEL + OFFSET;
        const float cy = (float)c.z * VOXEL + OFFSET;  // ref bug: x_offset for y
        const float m  = (lane < n) ? 1.0f : 0.0f;
        const float off_x = (v1.x - cx) * m;
        const float off_y = (v1.y - cy) * m;
        float* o = out_feat + (long long)p1 * FEAT_FLOATS + lane;
        __stcs(&o[0 * 32], off_x);
        __stcs(&o[1 * 32], off_y);
        __stcs(&o[2 * 32], v1.z * m);
        __stcs(&o[3 * 32], v1.w * m);
        __stcs(&o[4 * 32], (v1.x - s1x * invn) * m);
        __stcs(&o[5 * 32], (v1.y - s1y * invn) * m);
        __stcs(&o[6 * 32], (v1.z - s1z * invn) * m);
        __stcs(&o[7 * 32], off_x);
        __stcs(&o[8 * 32], off_y);
    }
}

extern "C" void kernel_launch(void* const* d_in, const int* in_sizes, int n_in,
                              void* d_out, int out_size)
{
    const float* pillars = (const float*)d_in[0];
    const int*   coors   = (const int*)d_in[1];
    const int*   npts    = (const int*)d_in[2];
    float* out = (float*)d_out;

    const long long P = (long long)in_sizes[2];          // npoints count = P
    const long long coors_elems = P * 4;
    const long long feat_elems  = P * 9 * MAX_PTS;

    float* out_coors = nullptr;
    float* out_feat  = out;
    if ((long long)out_size >= coors_elems + feat_elems) {
        out_coors = out;
        out_feat  = out + coors_elems;
    }

    const int blocks = (int)((P + PILLARS_PER_BLOCK - 1) / PILLARS_PER_BLOCK);
    pfn_fused_kernel<<<blocks, THREADS>>>(
        (const float4*)pillars, (const int4*)coors, npts, out_coors, out_feat, (int)P);
}

// round 15
// speedup vs baseline: 1.0251x; 1.0072x over previous
#include <cuda_runtime.h>
#include <cuda_bf16.h>
#include <cstdint>

// PFNLayer pillar feature decoration — FINAL (converged; 5 runs of this
// configuration at kernel 49.8-51.6us / total 53.7-54.9us, the noise band).
// Fused single kernel, 2 pillars per warp, MLP=2 at ~86% occupancy (regs 32),
// streaming loads (__ldcs) and stores (__stcs), no smem, no barriers.
// 336 MB nominal traffic at ~6.7 TB/s = ~84% of HBM3e spec — the achieved
// mixed read/write roofline on sm_103a.
// Falsified alternatives: smem-staged writes (-38%), MLP=3/4 (occupancy
// crash), default-cached reads (write stream thrashes L2), front-batching
// (neutral-to-worse), occupancy caps (worse), separate coors kernel (+6us),
// 512-thread blocks (neutral).
//
//   pillars:  (P, 32, 4) f32
//   coors:    (P, 4)     i32
//   npoints:  (P,)       i32
// Output buffer: [coors cast to f32 (P*4)] ++ [features (P,9,32) f32]
// features:
//   ch0 = x - (coors[:,1]*0.16 + 0.08)
//   ch1 = y - (coors[:,2]*0.16 + 0.08)   // upstream bug: x_offset for y, replicated
//   ch2 = z, ch3 = w
//   ch4..6 = xyz - mean_xyz  (mean = sum over ALL 32 slots / true count n)
//   ch7 = ch0, ch8 = ch1
//   channels zeroed for slot j >= n

static constexpr int MAX_PTS = 32;
static constexpr float VOXEL = 0.16f;
static constexpr float OFFSET = 0.08f;   // voxel/2 + 0.0, used for BOTH x and y (ref bug)

static constexpr int WARPS_PER_BLOCK = 8;
static constexpr int PILLARS_PER_WARP = 2;
static constexpr int PILLARS_PER_BLOCK = WARPS_PER_BLOCK * PILLARS_PER_WARP;  // 16
static constexpr int FEAT_FLOATS = 9 * MAX_PTS;          // 288 floats per pillar

__global__ void __launch_bounds__(256)
pfn_fused_kernel(const float4* __restrict__ pillars,   // (P*32) float4
                 const int4*   __restrict__ coors,     // (P) int4
                 const int*    __restrict__ npts,      // (P)
                 float*        __restrict__ out_coors, // (P*4) or nullptr
                 float*        __restrict__ out_feat,  // (P*9*32)
                 int P)
{
    const int warp_in_block = threadIdx.x >> 5;
    const int lane = threadIdx.x & 31;
    const long long pbase = (long long)blockIdx.x * PILLARS_PER_BLOCK
                          + warp_in_block * PILLARS_PER_WARP;
    const int p0 = (int)pbase;
    const int p1 = p0 + 1;
    const bool has0 = (p0 < P);
    const bool has1 = (p1 < P);

    // two independent 128-bit loads per lane — MLP=2, both streaming
    float4 v0 = make_float4(0.f, 0.f, 0.f, 0.f);
    float4 v1 = make_float4(0.f, 0.f, 0.f, 0.f);
    if (has0) v0 = __ldcs(&pillars[(long long)p0 * MAX_PTS + lane]);
    if (has1) v1 = __ldcs(&pillars[(long long)p1 * MAX_PTS + lane]);

    // interleaved warp reductions (sum over ALL 32 slots, per reference)
    float s0x = v0.x, s0y = v0.y, s0z = v0.z;
    float s1x = v1.x, s1y = v1.y, s1z = v1.z;
    #pragma unroll
    for (int ofs = 16; ofs > 0; ofs >>= 1) {
        s0x += __shfl_xor_sync(0xFFFFFFFFu, s0x, ofs);
        s1x += __shfl_xor_sync(0xFFFFFFFFu, s1x, ofs);
        s0y += __shfl_xor_sync(0xFFFFFFFFu, s0y, ofs);
        s1y += __shfl_xor_sync(0xFFFFFFFFu, s1y, ofs);
        s0z += __shfl_xor_sync(0xFFFFFFFFu, s0z, ofs);
        s1z += __shfl_xor_sync(0xFFFFFFFFu, s1z, ofs);
    }

    if (has0) {
        const int   n    = __ldg(&npts[p0]);
        const float invn = 1.0f / (float)n;
        const int4  c    = __ldg(&coors[p0]);
        if (out_coors != nullptr && lane == 0) {
            float4 cf = make_float4((float)c.x, (float)c.y, (float)c.z, (float)c.w);
            __stcs(reinterpret_cast<float4*>(out_coors) + p0, cf);
        }
        const float cx = (float)c.y * VOXEL + OFFSET;
        const float cy = (float)c.z * VOXEL + OFFSET;  // ref bug: x_offset for y
        const float m  = (lane < n) ? 1.0f : 0.0f;
        const float off_x = (v0.x - cx) * m;
        const float off_y = (v0.y - cy) * m;
        float* o = out_feat + (long long)p0 * FEAT_FLOATS + lane;
        __stcs(&o[0 * 32], off_x);
        __stcs(&o[1 * 32], off_y);
        __stcs(&o[2 * 32], v0.z * m);
        __stcs(&o[3 * 32], v0.w * m);
        __stcs(&o[4 * 32], (v0.x - s0x * invn) * m);
        __stcs(&o[5 * 32], (v0.y - s0y * invn) * m);
        __stcs(&o[6 * 32], (v0.z - s0z * invn) * m);
        __stcs(&o[7 * 32], off_x);
        __stcs(&o[8 * 32], off_y);
    }

    if (has1) {
        const int   n    = __ldg(&npts[p1]);
        const float invn = 1.0f / (float)n;
        const int4  c    = __ldg(&coors[p1]);
        if (out_coors != nullptr && lane == 0) {
            float4 cf = make_float4((float)c.x, (float)c.y, (float)c.z, (float)c.w);
            __stcs(reinterpret_cast<float4*>(out_coors) + p1, cf);
        }
        const float cx = (float)c.y * VOXEL + OFFSET;
        const float cy = (float)c.z * VOXEL + OFFSET;  // ref bug: x_offset for y
        const float m  = (lane < n) ? 1.0f : 0.0f;
        const float off_x = (v1.x - cx) * m;
        const float off_y = (v1.y - cy) * m;
        float* o = out_feat + (long long)p1 * FEAT_FLOATS + lane;
        __stcs(&o[0 * 32], off_x);
        __stcs(&o[1 * 32], off_y);
        __stcs(&o[2 * 32], v1.z * m);
        __stcs(&o[3 * 32], v1.w * m);
        __stcs(&o[4 * 32], (v1.x - s1x * invn) * m);
        __stcs(&o[5 * 32], (v1.y - s1y * invn) * m);
        __stcs(&o[6 * 32], (v1.z - s1z * invn) * m);
        __stcs(&o[7 * 32], off_x);
        __stcs(&o[8 * 32], off_y);
    }
}

extern "C" void kernel_launch(void* const* d_in, const int* in_sizes, int n_in,
                              void* d_out, int out_size)
{
    const float* pillars = (const float*)d_in[0];
    const int*   coors   = (const int*)d_in[1];
    const int*   npts    = (const int*)d_in[2];
    float* out = (float*)d_out;

    const long long P = (long long)in_sizes[2];          // npoints count = P
    const long long coors_elems = P * 4;
    const long long feat_elems  = P * 9 * MAX_PTS;

    float* out_coors = nullptr;
    float* out_feat  = out;
    if ((long long)out_size >= coors_elems + feat_elems) {
        out_coors = out;
        out_feat  = out + coors_elems;
    }

    const int blocks = (int)((P + PILLARS_PER_BLOCK - 1) / PILLARS_PER_BLOCK);
    pfn_fused_kernel<<<blocks, 256>>>(
        (const float4*)pillars, (const int4*)coors, npts, out_coors, out_feat, (int)P);
}